// round 10
// baseline (speedup 1.0000x reference)
#include <cuda_runtime.h>

#define MARGIN  1.9f
#define GRID    592              // 4 blocks/SM on 148 SMs, all wave-1 resident
#define NMAXE   1024
#define BSCALE  8.0f             // 256 buckets over d in [0,32)

// Scratch (no allocation allowed)
__device__ float g_dot[640 * 640];   // full dot products (mirror filled from upper tiles)
__device__ float g_sq[NMAXE];        // = diag(dot), written by diagonal tiles
__device__ int   g_lab[NMAXE];
__device__ float g_bsum[GRID];
__device__ int   g_bcnt[GRID];
__device__ int   g_bval[GRID];
__device__ int   g_bar1 = 0;
__device__ int   g_bar2 = 0;

// Fused kernel, grid=592:
//  phase 1: blocks 0..209 : UPPER-TRIANGLE 32x32 dot tiles (dot is symmetric;
//                           off-diag tiles mirror via smem transpose; diagonal
//                           tiles emit g_sq).  block 210: labels. 211..591 idle.
//  grid barrier
//  phase 2: block b -> anchors i = b, b+592. Counting-sort histogram of the
//           negatives, prefix scans, O(1)+boundary-bucket query per positive.
//  phase 3: last block reduces partials -> out[4], resets barriers
__global__ void __launch_bounds__(256, 4)
fused_triplet_kernel(const float* __restrict__ e, const int* __restrict__ lab32,
                     float* __restrict__ out, int n) {
    __shared__ float As[32 * 132];   // A tile, 16.9 KB (phase 1)
    __shared__ float Bs[128 * 32];   // B tile k-major, 16 KB (also transpose buf)
    // phase 2 histogram structures
    __shared__ int   hcnt[256];
    __shared__ int   pcs[257];       // exclusive prefix of counts; pcs[256]=Ntot
    __shared__ int   cur[256];       // scatter cursors
    __shared__ float pvs[256];       // exclusive prefix of per-bucket value sums
    __shared__ float bval[704];      // negatives grouped by bucket
    __shared__ int   swi[8], swi2[8];
    __shared__ float swf[8], swf2[8];
    __shared__ int   s_old, s_is64;
    __shared__ float wsum[8];
    __shared__ int   wcnt[8];

    const int b    = blockIdx.x;
    const int tid  = threadIdx.x;
    const int lane = tid & 31;
    const int wid  = tid >> 5;
    const float4* e4 = (const float4*)e;   // 32 float4 per embedding row

    const int tiles_x    = n >> 5;                        // 20
    const int tri_blocks = (tiles_x * (tiles_x + 1)) / 2; // 210
    const int lab_block  = tri_blocks;                    // 210

    // ================= phase 1 =================
    if (b < tri_blocks) {
        // invert triangular index -> (ti, tj), tj >= ti
        int ti = 0, rrem = b;
        #pragma unroll 1
        for (; ti < tiles_x; ti++) {
            int cnt = tiles_x - ti;
            if (rrem < cnt) break;
            rrem -= cnt;
        }
        const int tj = ti + rrem;

        const int tx = tid & 15;     // col pair (cols 2tx, 2tx+1)
        const int ty = tid >> 4;     // row pair (rows 2ty, 2ty+1)

        #pragma unroll
        for (int r = 0; r < 4; r++) {
            int lin = tid + r * 256;
            int row = lin >> 5;
            int c4  = lin & 31;
            float4 v = e4[(size_t)(ti * 32 + row) * 32 + c4];
            *(float4*)&As[row * 132 + c4 * 4] = v;
        }
        #pragma unroll
        for (int r = 0; r < 4; r++) {
            int lin = tid + r * 256;
            int j   = lin & 31;
            int c4  = lin >> 5;
            float4 v = e4[(size_t)(tj * 32 + j) * 32 + c4];
            Bs[(c4 * 4 + 0) * 32 + j] = v.x;
            Bs[(c4 * 4 + 1) * 32 + j] = v.y;
            Bs[(c4 * 4 + 2) * 32 + j] = v.z;
            Bs[(c4 * 4 + 3) * 32 + j] = v.w;
        }
        __syncthreads();

        float acc00 = 0.f, acc01 = 0.f, acc10 = 0.f, acc11 = 0.f;
        #pragma unroll 4
        for (int k4 = 0; k4 < 32; k4++) {
            float4 a0 = *(const float4*)&As[(2 * ty + 0) * 132 + 4 * k4];
            float4 a1 = *(const float4*)&As[(2 * ty + 1) * 132 + 4 * k4];
            float2 b0 = *(const float2*)&Bs[(4 * k4 + 0) * 32 + 2 * tx];
            float2 b1 = *(const float2*)&Bs[(4 * k4 + 1) * 32 + 2 * tx];
            float2 b2 = *(const float2*)&Bs[(4 * k4 + 2) * 32 + 2 * tx];
            float2 b3 = *(const float2*)&Bs[(4 * k4 + 3) * 32 + 2 * tx];
            acc00 = fmaf(a0.x, b0.x, acc00);
            acc01 = fmaf(a0.x, b0.y, acc01);
            acc10 = fmaf(a1.x, b0.x, acc10);
            acc11 = fmaf(a1.x, b0.y, acc11);
            acc00 = fmaf(a0.y, b1.x, acc00);
            acc01 = fmaf(a0.y, b1.y, acc01);
            acc10 = fmaf(a1.y, b1.x, acc10);
            acc11 = fmaf(a1.y, b1.y, acc11);
            acc00 = fmaf(a0.z, b2.x, acc00);
            acc01 = fmaf(a0.z, b2.y, acc01);
            acc10 = fmaf(a1.z, b2.x, acc10);
            acc11 = fmaf(a1.z, b2.y, acc11);
            acc00 = fmaf(a0.w, b3.x, acc00);
            acc01 = fmaf(a0.w, b3.y, acc01);
            acc10 = fmaf(a1.w, b3.x, acc10);
            acc11 = fmaf(a1.w, b3.y, acc11);
        }
        const int row0 = ti * 32 + 2 * ty;
        const int col0 = tj * 32 + 2 * tx;
        *(float2*)&g_dot[(size_t)(row0 + 0) * n + col0] = make_float2(acc00, acc01);
        *(float2*)&g_dot[(size_t)(row0 + 1) * n + col0] = make_float2(acc10, acc11);

        if (ti == tj) {
            if (2 * ty     == 2 * tx    ) g_sq[row0]     = acc00;
            if (2 * ty     == 2 * tx + 1) g_sq[row0]     = acc01;
            if (2 * ty + 1 == 2 * tx    ) g_sq[row0 + 1] = acc10;
            if (2 * ty + 1 == 2 * tx + 1) g_sq[row0 + 1] = acc11;
        } else {
            float* Tr = Bs;                  // reuse: [32][33]
            __syncthreads();
            Tr[(2 * tx + 0) * 33 + 2 * ty + 0] = acc00;
            Tr[(2 * tx + 1) * 33 + 2 * ty + 0] = acc01;
            Tr[(2 * tx + 0) * 33 + 2 * ty + 1] = acc10;
            Tr[(2 * tx + 1) * 33 + 2 * ty + 1] = acc11;
            __syncthreads();
            int trow = tid >> 3;
            int tc4  = tid & 7;
            float4 mv;
            mv.x = Tr[trow * 33 + tc4 * 4 + 0];
            mv.y = Tr[trow * 33 + tc4 * 4 + 1];
            mv.z = Tr[trow * 33 + tc4 * 4 + 2];
            mv.w = Tr[trow * 33 + tc4 * 4 + 3];
            *(float4*)&g_dot[(size_t)(tj * 32 + trow) * n + ti * 32 + tc4 * 4] = mv;
        }
    } else if (b == lab_block) {
        if (tid == 0) s_is64 = 1;
        __syncthreads();
        for (int idx = tid; idx < n / 2; idx += 256)
            if (lab32[2 * idx + 1] != 0) atomicExch(&s_is64, 0);
        __syncthreads();
        const bool is64 = (s_is64 != 0);
        for (int i2 = tid; i2 < n; i2 += 256)
            g_lab[i2] = is64 ? lab32[2 * i2] : lab32[i2];
    }

    // ================= grid barrier =================
    __threadfence();
    __syncthreads();
    if (tid == 0) {
        atomicAdd(&g_bar1, 1);
        volatile int* vb = &g_bar1;
        while (*vb < GRID) { __nanosleep(32); }
    }
    __syncthreads();

    // ================= phase 2: anchors via counting sort =================
    float lsum = 0.f;
    int   lcnt = 0;
    int   vtot = 0;

    for (int i = b; i < n; i += GRID) {
        const int   li  = g_lab[i];
        const float sqi = g_sq[i];
        const float* __restrict__ drow = &g_dot[(size_t)i * n];

        __syncthreads();                 // prev anchor's structures fully consumed
        hcnt[tid] = 0;
        __syncthreads();

        // classify this thread's j slots; negatives -> histogram
        float dvs[3];
        int   typ[3];                    // 0 = neg, 1 = pos, 2 = skip
        #pragma unroll
        for (int s = 0; s < 3; s++) {
            int j = tid + s * 256;
            typ[s] = 2; dvs[s] = 0.f;
            if (j < n) {
                float dv = sqrtf(fmaxf(sqi + g_sq[j] - 2.0f * drow[j], 0.0f));
                dvs[s] = dv;
                if (g_lab[j] == li) {
                    typ[s] = (j == i) ? 2 : 1;
                } else {
                    typ[s] = 0;
                    int bb = min(255, (int)(dv * BSCALE));
                    atomicAdd(&hcnt[bb], 1);
                }
            }
        }
        __syncthreads();

        // exclusive scan of counts -> pcs, cursors
        int vcnt = hcnt[tid];
        int inc = vcnt;
        #pragma unroll
        for (int off = 1; off < 32; off <<= 1) {
            int t = __shfl_up_sync(0xFFFFFFFFu, inc, off);
            if (lane >= off) inc += t;
        }
        if (lane == 31) swi[wid] = inc;
        __syncthreads();
        if (tid < 8) {
            int o = 0;
            for (int k = 0; k < tid; k++) o += swi[k];
            swi2[tid] = o;
        }
        __syncthreads();
        int exc = inc - vcnt + swi2[wid];
        pcs[tid] = exc;
        cur[tid] = exc;
        if (tid == 255) pcs[256] = exc + vcnt;
        __syncthreads();

        // scatter negatives grouped by bucket
        #pragma unroll
        for (int s = 0; s < 3; s++) {
            if (typ[s] == 0) {
                int bb = min(255, (int)(dvs[s] * BSCALE));
                int slot = atomicAdd(&cur[bb], 1);
                bval[slot] = dvs[s];
            }
        }
        __syncthreads();

        // per-bucket value sums -> exclusive scan pvs
        float sv = 0.f;
        {
            int s0 = pcs[tid], s1 = pcs[tid + 1];
            for (int k = s0; k < s1; k++) sv += bval[k];
        }
        float fin = sv;
        #pragma unroll
        for (int off = 1; off < 32; off <<= 1) {
            float t = __shfl_up_sync(0xFFFFFFFFu, fin, off);
            if (lane >= off) fin += t;
        }
        if (lane == 31) swf[wid] = fin;
        __syncthreads();
        if (tid < 8) {
            float o = 0.f;
            for (int k = 0; k < tid; k++) o += swf[k];
            swf2[tid] = o;
        }
        __syncthreads();
        pvs[tid] = fin - sv + swf2[wid];
        __syncthreads();

        // positives: O(1) prefix lookup + boundary-bucket exact scan
        const int Ntot = pcs[256];
        #pragma unroll
        for (int s = 0; s < 3; s++) {
            if (typ[s] == 1) {
                float t = dvs[s] + MARGIN;
                int bb = min(255, (int)(t * BSCALE));
                int cnt = pcs[bb];
                float sm = pvs[bb];
                int e1 = pcs[bb + 1];
                for (int k = pcs[bb]; k < e1; k++) {
                    float vv = bval[k];
                    if (vv < t) { cnt++; sm += vv; }
                }
                lcnt += cnt;
                lsum += (float)cnt * t - sm;
            }
        }
        vtot += (n - 1 - Ntot) * Ntot;   // P = n-1-Ntot
    }

    // block reduce
    #pragma unroll
    for (int off = 16; off; off >>= 1) {
        lsum += __shfl_down_sync(0xFFFFFFFFu, lsum, off);
        lcnt += __shfl_down_sync(0xFFFFFFFFu, lcnt, off);
    }
    if (lane == 0) { wsum[wid] = lsum; wcnt[wid] = lcnt; }
    __syncthreads();
    if (tid == 0) {
        float s = 0.f; int c = 0;
        #pragma unroll
        for (int w = 0; w < 8; w++) { s += wsum[w]; c += wcnt[w]; }
        g_bsum[b] = s;
        g_bcnt[b] = c;
        g_bval[b] = vtot;
    }

    // ================= phase 3: last block finalizes =================
    __threadfence();
    __syncthreads();
    if (tid == 0) s_old = atomicAdd(&g_bar2, 1);
    __syncthreads();
    if (s_old == GRID - 1) {
        float s = 0.f; int c = 0, v = 0;
        for (int idx = tid; idx < GRID; idx += 256) {
            s += g_bsum[idx];
            c += g_bcnt[idx];
            v += g_bval[idx];
        }
        #pragma unroll
        for (int off = 16; off; off >>= 1) {
            s += __shfl_down_sync(0xFFFFFFFFu, s, off);
            c += __shfl_down_sync(0xFFFFFFFFu, c, off);
            v += __shfl_down_sync(0xFFFFFFFFu, v, off);
        }
        __shared__ float fs[8];
        __shared__ int   fc[8], fv[8];
        if (lane == 0) { fs[wid] = s; fc[wid] = c; fv[wid] = v; }
        __syncthreads();
        if (tid == 0) {
            float total = 0.f; int cnt = 0, val = 0;
            #pragma unroll
            for (int w = 0; w < 8; w++) { total += fs[w]; cnt += fc[w]; val += fv[w]; }
            float num_non   = (float)cnt;
            float num_valid = (float)val;
            out[0] = (cnt > 0) ? total / fmaxf(num_non, 1.0f) : 0.0f;
            out[1] = num_valid;
            out[2] = num_non;
            out[3] = num_non / (num_valid + 1e-16f);
            g_bar1 = 0;
            g_bar2 = 0;
            __threadfence();
        }
    }
}

extern "C" void kernel_launch(void* const* d_in, const int* in_sizes, int n_in,
                              void* d_out, int out_size) {
    const float* e   = (const float*)d_in[0];   // embeddings [8,80,128] fp32
    const int*   lab = (const int*)d_in[1];     // labels (int64 or int32 view)
    int n = in_sizes[1];                        // 640

    fused_triplet_kernel<<<GRID, 256>>>(e, lab, (float*)d_out, n);
}